// round 1
// baseline (speedup 1.0000x reference)
#include <cuda_runtime.h>
#include <cstdint>

// Fused edge-MLP:
//   x = [e | h[src]+h[dst]]            [E, 256]
//   x = leaky(x @ W1^T + b1)           [E, 128]
//   x = leaky(x @ W2^T + b2)           [E, 128]
//   out = leaky(x @ W3^T + b3)         [E, 128]
//
// One CTA = 32 edges, 128 threads (thread j = output feature j).
// x staged in shared as [k][edge] so a thread's 16 edge-pair MACs per k are
// 8-byte broadcast LDS + packed fma.rn.f32x2 (FFMA2, 2x fp32 rate).
// Weights staged in shared in 32-wide K chunks (coalesced LDG, conflict-free LDS).

#define TILE_E 32
#define NT     128
#define DD     128
#define PADX   34   // even (8B-aligned pairs), 34%32 != 0 avoids k-store conflicts
#define PADW   33

__device__ __forceinline__ unsigned long long pack2(float a, float b) {
    unsigned long long r;
    asm("mov.b64 %0, {%1,%2};" : "=l"(r) : "f"(a), "f"(b));
    return r;
}
__device__ __forceinline__ void unpack2(unsigned long long v, float& a, float& b) {
    asm("mov.b64 {%0,%1}, %2;" : "=f"(a), "=f"(b) : "l"(v));
}
__device__ __forceinline__ unsigned long long fma2(unsigned long long a,
                                                   unsigned long long b,
                                                   unsigned long long c) {
    unsigned long long r;
    asm("fma.rn.f32x2 %0, %1, %2, %3;" : "=l"(r) : "l"(a), "l"(b), "l"(c));
    return r;
}

__device__ __forceinline__ float leaky(float v) {
    return v >= 0.0f ? v : 0.01f * v;
}

// One linear layer: reads in_sh [Kin][PADX], writes either out_sh [DD][PADX]
// (post-activation, next layer's input) or global out (final layer).
__device__ __forceinline__ void layer(const float* __restrict__ in_sh, int Kin,
                                      const float* __restrict__ W,
                                      const float* __restrict__ b,
                                      float* wsh, float* out_sh,
                                      float* __restrict__ out_g,
                                      int base, int evalid) {
    const int j = threadIdx.x;
    unsigned long long acc[TILE_E / 2];
    const float bj = b[j];
#pragma unroll
    for (int p = 0; p < TILE_E / 2; ++p) acc[p] = pack2(bj, bj);

    const int nch = Kin >> 5;  // chunks of 32 k
    for (int c = 0; c < nch; ++c) {
        __syncthreads();  // prior chunk (and prior layer's in/out) fully consumed
        // Stage W[:, c*32 : c*32+32] -> wsh[row][kk], coalesced float4 LDG.
#pragma unroll
        for (int p = 0; p < 8; ++p) {
            int i   = threadIdx.x + p * NT;  // 0..1023
            int row = i >> 3;
            int seg = i & 7;
            float4 v = *(const float4*)(W + (size_t)row * Kin + c * 32 + seg * 4);
            float* d = wsh + row * PADW + seg * 4;
            d[0] = v.x; d[1] = v.y; d[2] = v.z; d[3] = v.w;
        }
        __syncthreads();

        const float* xcol = in_sh + (c * 32) * PADX;
#pragma unroll
        for (int kk = 0; kk < 32; ++kk) {
            float w = wsh[j * PADW + kk];           // conflict-free (stride 33)
            unsigned long long w2 = pack2(w, w);
            const float* xr = xcol + kk * PADX;
#pragma unroll
            for (int p = 0; p < TILE_E / 2; ++p) {
                unsigned long long x2 = *(const unsigned long long*)(xr + 2 * p);
                acc[p] = fma2(x2, w2, acc[p]);      // 2 edges per FFMA2
            }
        }
    }

    if (out_g) {
#pragma unroll
        for (int p = 0; p < TILE_E / 2; ++p) {
            float a, bv;
            unpack2(acc[p], a, bv);
            a  = leaky(a);
            bv = leaky(bv);
            int e0 = 2 * p;
            if (e0 < evalid)     out_g[(size_t)(base + e0) * DD + j] = a;
            if (e0 + 1 < evalid) out_g[(size_t)(base + e0 + 1) * DD + j] = bv;
        }
    } else {
        __syncthreads();  // in_sh fully consumed before out_sh may alias it
#pragma unroll
        for (int p = 0; p < TILE_E / 2; ++p) {
            float a, bv;
            unpack2(acc[p], a, bv);
            *(unsigned long long*)(out_sh + j * PADX + 2 * p) =
                pack2(leaky(a), leaky(bv));
        }
    }
}

__global__ __launch_bounds__(NT)
void edge_mlp_kernel(const float* __restrict__ e_in,
                     const float* __restrict__ h,
                     const int* __restrict__ src,
                     const int* __restrict__ dst,
                     const float* __restrict__ W1, const float* __restrict__ b1,
                     const float* __restrict__ W2, const float* __restrict__ b2,
                     const float* __restrict__ W3, const float* __restrict__ b3,
                     float* __restrict__ out, int E) {
    extern __shared__ float smem[];
    float* xs  = smem;                  // [256][PADX]
    float* ys  = xs + 256 * PADX;       // [128][PADX]
    float* wsh = ys + DD * PADX;        // [128][PADW]
    int*   sidx = (int*)(wsh + DD * PADW);  // [2*TILE_E]

    const int tid  = threadIdx.x;
    const int base = blockIdx.x * TILE_E;
    const int evalid = min(TILE_E, E - base);

    if (tid < TILE_E) {
        sidx[tid] = (tid < evalid) ? src[base + tid] : 0;
    } else if (tid < 2 * TILE_E) {
        int t2 = tid - TILE_E;
        sidx[TILE_E + t2] = (t2 < evalid) ? dst[base + t2] : 0;
    }
    __syncthreads();

    // Build x = [e | h[src]+h[dst]] into xs[k][edge], coalesced LDG per edge.
    for (int ee = 0; ee < TILE_E; ++ee) {
        float ev = 0.0f, hv = 0.0f;
        if (ee < evalid) {
            int eg = base + ee;
            ev = e_in[(size_t)eg * DD + tid];
            hv = h[(size_t)sidx[ee] * DD + tid] +
                 h[(size_t)sidx[TILE_E + ee] * DD + tid];
        }
        xs[tid * PADX + ee]        = ev;
        xs[(DD + tid) * PADX + ee] = hv;
    }
    // layer() starts with __syncthreads(), covering the gather stores.

    layer(xs, 256, W1, b1, wsh, ys, nullptr, base, evalid);  // xs -> ys
    layer(ys, 128, W2, b2, wsh, xs, nullptr, base, evalid);  // ys -> xs[0:128]
    layer(xs, 128, W3, b3, wsh, nullptr, out, base, evalid); // xs -> gmem
}

extern "C" void kernel_launch(void* const* d_in, const int* in_sizes, int n_in,
                              void* d_out, int out_size) {
    const float* e_in = (const float*)d_in[0];
    const float* h    = (const float*)d_in[1];
    const int*   src  = (const int*)d_in[2];
    const int*   dst  = (const int*)d_in[3];
    const float* W1   = (const float*)d_in[4];
    const float* b1   = (const float*)d_in[5];
    const float* W2   = (const float*)d_in[6];
    const float* b2   = (const float*)d_in[7];
    const float* W3   = (const float*)d_in[8];
    const float* b3   = (const float*)d_in[9];
    float* out = (float*)d_out;

    const int E = in_sizes[0] / DD;

    const int smem_bytes = (256 * PADX + DD * PADX + DD * PADW) * (int)sizeof(float)
                         + 2 * TILE_E * (int)sizeof(int);
    cudaFuncSetAttribute(edge_mlp_kernel,
                         cudaFuncAttributeMaxDynamicSharedMemorySize, smem_bytes);

    const int grid = (E + TILE_E - 1) / TILE_E;
    edge_mlp_kernel<<<grid, NT, smem_bytes>>>(e_in, h, src, dst,
                                              W1, b1, W2, b2, W3, b3, out, E);
}